// round 7
// baseline (speedup 1.0000x reference)
#include <cuda_runtime.h>

#define BB 32
#define CC 256
#define TT 4096
#define NH 8
#define DH 64
#define DK 512     // NH*DH
#define JSPLIT 16
#define JB 256     // j per block
#define JBQ 64     // float4 (16B) units per block j-range

typedef unsigned long long u64;

// Scratch (allocation-free per harness rules)
__device__ float g_qW[BB * NH * CC];            // scale-folded q @ Wkv_k
__device__ float g_pm[JSPLIT * BB * NH];        // block-local softmax max
__device__ float g_ps[JSPLIT * BB * NH];        // block-local softmax sum
__device__ float g_pacc[JSPLIT * BB * NH * CC]; // unnormalized attn·x partials
__device__ float g_xa[BB * NH * CC];            // combined xattn
__device__ float g_oh[BB * DK];                 // v-projection intermediate

// ---- packed f32x2 helpers (Blackwell FFMA2: 2x fp32 FMA per instruction) ----
__device__ __forceinline__ u64 pk(float a, float b) {
    u64 v; asm("mov.b64 %0,{%1,%2};" : "=l"(v) : "f"(a), "f"(b)); return v;
}
__device__ __forceinline__ float2 upk(u64 v) {
    float2 f; asm("mov.b64 {%0,%1},%2;" : "=f"(f.x), "=f"(f.y) : "l"(v)); return f;
}
__device__ __forceinline__ void ffma2(u64& d, u64 a, u64 b) {
    asm("fma.rn.f32x2 %0,%1,%2,%0;" : "+l"(d) : "l"(a), "l"(b));
}

// ---------------------------------------------------------------------------
// Kernel A: per (n,b): q[n,:] = query@Wq.T + bq ; qW[b,n,c] = scale * q·Wkv_k[:,c]
// grid = (8 n, 32 b), 256 threads
// ---------------------------------------------------------------------------
__global__ void k_prep(const float* __restrict__ query,
                       const float* __restrict__ Wq,
                       const float* __restrict__ bq,
                       const float* __restrict__ Wkv) {
    const int n = blockIdx.x, b = blockIdx.y;
    const int tid = threadIdx.x, wid = tid >> 5, lane = tid & 31;
    __shared__ float qin[CC];
    __shared__ float qs[DH];

    qin[tid] = query[b * CC + tid];
    __syncthreads();

    const float4* qv = (const float4*)qin;
    for (int d = wid; d < DH; d += 8) {
        const float4* wr = (const float4*)(Wq + (size_t)(n * DH + d) * CC);
        float s = 0.f;
#pragma unroll
        for (int i = 0; i < 2; ++i) {
            const float4 w = wr[lane + i * 32];
            const float4 q4 = qv[lane + i * 32];
            s += w.x * q4.x + w.y * q4.y + w.z * q4.z + w.w * q4.w;
        }
#pragma unroll
        for (int o = 16; o; o >>= 1) s += __shfl_xor_sync(~0u, s, o);
        if (!lane) qs[d] = s + bq[n * DH + d];
    }
    __syncthreads();

    const float* wbase = Wkv + (size_t)(n * DH) * CC + tid;
    float s = 0.f;
#pragma unroll 8
    for (int d = 0; d < DH; ++d) s += qs[d] * wbase[(size_t)d * CC];
    g_qW[(b * NH + n) * CC + tid] = s * 0.125f;  // 1/sqrt(64)
}

// ---------------------------------------------------------------------------
// Kernel B (fused): per (b, j-range of 256):
//   phase1: logits l[8][256] = qW @ x-tile       (x-tile: 256c x 256j, DRAM)
//   phase2: local softmax -> p (unnormalized), m_blk, s_blk
//   phase3: pacc[8][256c] = p @ x-tile^T          (x-tile re-read from L2)
// grid = (16 jr, 32 b), 256 threads.
// ---------------------------------------------------------------------------
__global__ void __launch_bounds__(256, 2) k_fused(const float* __restrict__ x) {
    const int jr = blockIdx.x, b = blockIdx.y;
    const int tid = threadIdx.x, lane = tid & 31, wid = tid >> 5;
    const int cq = tid >> 6;    // c-quarter 0..3 (64 rows each)
    const int jql = tid & 63;   // local 16B-unit j index
    const int jq0 = jr * JBQ;

    __shared__ u64 qw2[CC][NH];            // packed {w,w}, 16 KB
    __shared__ u64 lbuf[4][64][NH][2];     // logit partials, 32 KB
    __shared__ float ps[NH][JB];           // logits -> exp(l-m), 8 KB

    for (int i = tid; i < CC * NH; i += 256) {
        const int c = i >> 3, n = i & 7;
        const float w = g_qW[(b * NH + n) * CC + c];
        qw2[c][n] = pk(w, w);
    }
    __syncthreads();

    // ---- phase 1: logits for this block's 256 j, c-quarter per thread-group
    u64 acc2[NH][2];
#pragma unroll
    for (int n = 0; n < NH; ++n) { acc2[n][0] = 0ull; acc2[n][1] = 0ull; }

    const ulonglong2* xp =
        (const ulonglong2*)(x + ((size_t)b * CC + cq * 64) * TT) + jq0 + jql;
#pragma unroll 4
    for (int i = 0; i < 64; ++i) {
        const ulonglong2 xv = xp[(size_t)i * (TT / 4)];
        const int c = cq * 64 + i;
#pragma unroll
        for (int n = 0; n < NH; ++n) {
            const u64 w = qw2[c][n];
            ffma2(acc2[n][0], w, xv.x);
            ffma2(acc2[n][1], w, xv.y);
        }
    }
#pragma unroll
    for (int n = 0; n < NH; ++n) {
        lbuf[cq][jql][n][0] = acc2[n][0];
        lbuf[cq][jql][n][1] = acc2[n][1];
    }
    __syncthreads();

    // ---- reduce over the 4 c-quarters: 512 (jj,n) pairs, 2 per thread
#pragma unroll
    for (int p = 2 * tid; p < 2 * tid + 2; ++p) {
        const int jj = p >> 3, n = p & 7;
        float2 a0 = upk(lbuf[0][jj][n][0]);
        float2 a1 = upk(lbuf[0][jj][n][1]);
#pragma unroll
        for (int q = 1; q < 4; ++q) {
            const float2 b0 = upk(lbuf[q][jj][n][0]);
            const float2 b1 = upk(lbuf[q][jj][n][1]);
            a0.x += b0.x; a0.y += b0.y; a1.x += b1.x; a1.y += b1.y;
        }
        ps[n][jj * 4 + 0] = a0.x; ps[n][jj * 4 + 1] = a0.y;
        ps[n][jj * 4 + 2] = a1.x; ps[n][jj * 4 + 3] = a1.y;
    }
    __syncthreads();

    // ---- phase 2: local softmax, warp wid owns head wid
    {
        float m = -1e30f;
        for (int j = lane; j < JB; j += 32) m = fmaxf(m, ps[wid][j]);
#pragma unroll
        for (int o = 16; o; o >>= 1) m = fmaxf(m, __shfl_xor_sync(~0u, m, o));
        float s = 0.f;
        for (int j = lane; j < JB; j += 32) {
            const float e = __expf(ps[wid][j] - m);
            ps[wid][j] = e;
            s += e;
        }
#pragma unroll
        for (int o = 16; o; o >>= 1) s += __shfl_xor_sync(~0u, s, o);
        if (!lane) {
            g_pm[(jr * BB + b) * NH + wid] = m;
            g_ps[(jr * BB + b) * NH + wid] = s;
        }
    }
    __syncthreads();

    // ---- phase 3: pacc[n][c] = sum_j p[n][j] * x[c][j]; warp owns 4 c-rows
    const ulonglong2* xq = (const ulonglong2*)(x + (size_t)b * CC * TT) + jq0;
    for (int it = 0; it < 8; ++it) {
        const int c0 = it * 32 + wid * 4;
        u64 a2[NH][4];
#pragma unroll
        for (int n = 0; n < NH; ++n)
#pragma unroll
            for (int cc = 0; cc < 4; ++cc) a2[n][cc] = 0ull;

#pragma unroll
        for (int st = 0; st < 2; ++st) {
            const int jq = lane + st * 32;
            ulonglong2 xv[4];
#pragma unroll
            for (int cc = 0; cc < 4; ++cc)
                xv[cc] = xq[(size_t)(c0 + cc) * (TT / 4) + jq];
#pragma unroll
            for (int n = 0; n < NH; ++n) {
                const ulonglong2 p2 = ((const ulonglong2*)&ps[n][0])[jq];
#pragma unroll
                for (int cc = 0; cc < 4; ++cc) {
                    ffma2(a2[n][cc], p2.x, xv[cc].x);
                    ffma2(a2[n][cc], p2.y, xv[cc].y);
                }
            }
        }
#pragma unroll
        for (int n = 0; n < NH; ++n)
#pragma unroll
            for (int cc = 0; cc < 4; ++cc) {
                const float2 f = upk(a2[n][cc]);
                float v = f.x + f.y;
#pragma unroll
                for (int o = 16; o; o >>= 1) v += __shfl_xor_sync(~0u, v, o);
                if (!lane)
                    g_pacc[((size_t)(jr * BB + b) * NH + n) * CC + c0 + cc] = v;
            }
    }
}

// ---------------------------------------------------------------------------
// Kernel C: combine split-softmax partials.
// grid = (8 n, 32 b), 256 threads (one per c).
// ---------------------------------------------------------------------------
__global__ void k_combine() {
    const int n = blockIdx.x, b = blockIdx.y;
    const int tid = threadIdx.x;
    __shared__ float sm_m[JSPLIT], sm_s[JSPLIT];

    if (tid < JSPLIT) {
        sm_m[tid] = g_pm[(tid * BB + b) * NH + n];
        sm_s[tid] = g_ps[(tid * BB + b) * NH + n];
    }
    __syncthreads();

    float M = -1e30f;
#pragma unroll
    for (int jr = 0; jr < JSPLIT; ++jr) M = fmaxf(M, sm_m[jr]);
    float S = 0.f;
#pragma unroll
    for (int jr = 0; jr < JSPLIT; ++jr) S += sm_s[jr] * __expf(sm_m[jr] - M);

    float acc = 0.f;
#pragma unroll
    for (int jr = 0; jr < JSPLIT; ++jr)
        acc += __expf(sm_m[jr] - M) *
               g_pacc[((size_t)(jr * BB + b) * NH + n) * CC + tid];
    g_xa[(b * NH + n) * CC + tid] = acc / S;
}

// ---------------------------------------------------------------------------
// Kernel D1: oh[b,nd] = Wkv_v[nd]·xa[b,n] + bkv_v[nd]
// grid = (32 b, 4 nd-tiles of 128), 128 threads = 4 warps, warp per row
// ---------------------------------------------------------------------------
__global__ void __launch_bounds__(128) k_out1(const float* __restrict__ Wkv,
                                              const float* __restrict__ bkv) {
    const int b = blockIdx.x, tile = blockIdx.y;
    const int tid = threadIdx.x, wid = tid >> 5, lane = tid & 31;
    __shared__ float xa[2 * CC];  // two heads for this nd-tile

    for (int i = tid; i < 2 * CC; i += 128)
        xa[i] = g_xa[b * NH * CC + tile * 2 * CC + i];
    __syncthreads();

    for (int ndl = wid; ndl < 128; ndl += 4) {
        const int nd = tile * 128 + ndl;
        const float4* wr = (const float4*)(Wkv + (size_t)(DK + nd) * CC);
        const float4* xr = (const float4*)(xa + (ndl >> 6) * CC);
        float s = 0.f;
#pragma unroll
        for (int i = 0; i < 2; ++i) {
            const float4 w = wr[lane + i * 32];
            const float4 v = xr[lane + i * 32];
            s += w.x * v.x + w.y * v.y + w.z * v.z + w.w * v.w;
        }
#pragma unroll
        for (int o = 16; o; o >>= 1) s += __shfl_xor_sync(~0u, s, o);
        if (!lane) g_oh[b * DK + nd] = s + bkv[DK + nd];
    }
}

// ---------------------------------------------------------------------------
// Kernel D2: y[b,o] = relu(oh[b]·Wfc[o] + bfc[o])
// grid = (32 b, 2 o-halves of 128), 256 threads = 8 warps, warp per row
// ---------------------------------------------------------------------------
__global__ void __launch_bounds__(256) k_out2(const float* __restrict__ Wfc,
                                              const float* __restrict__ bfc,
                                              float* __restrict__ out) {
    const int b = blockIdx.x, half = blockIdx.y;
    const int tid = threadIdx.x, wid = tid >> 5, lane = tid & 31;
    __shared__ float oh[DK];

    for (int i = tid; i < DK; i += 256) oh[i] = g_oh[b * DK + i];
    __syncthreads();

    const float4* ov = (const float4*)oh;
    for (int ol = wid; ol < 128; ol += 8) {
        const int o = half * 128 + ol;
        const float4* wr = (const float4*)(Wfc + (size_t)o * DK);
        float s = 0.f;
#pragma unroll
        for (int i = 0; i < 4; ++i) {
            const float4 w = wr[lane + i * 32];
            const float4 v = ov[lane + i * 32];
            s += w.x * v.x + w.y * v.y + w.z * v.z + w.w * v.w;
        }
#pragma unroll
        for (int oo = 16; oo; oo >>= 1) s += __shfl_xor_sync(~0u, s, oo);
        if (!lane) out[b * CC + o] = fmaxf(s + bfc[o], 0.f);
    }
}

// ---------------------------------------------------------------------------
extern "C" void kernel_launch(void* const* d_in, const int* in_sizes, int n_in,
                              void* d_out, int out_size) {
    const float* x     = (const float*)d_in[0];  // (32,256,64,64)
    const float* query = (const float*)d_in[1];  // (32,256)
    const float* Wkv   = (const float*)d_in[2];  // (1024,256)
    const float* bkv   = (const float*)d_in[3];  // (1024)
    const float* Wq    = (const float*)d_in[4];  // (512,256)
    const float* bq    = (const float*)d_in[5];  // (512)
    const float* Wfc   = (const float*)d_in[6];  // (256,512)
    const float* bfc   = (const float*)d_in[7];  // (256)
    float* out = (float*)d_out;                  // (32,256)

    k_prep<<<dim3(NH, BB), 256>>>(query, Wq, bq, Wkv);
    k_fused<<<dim3(JSPLIT, BB), 256>>>(x);
    k_combine<<<dim3(NH, BB), 256>>>();
    k_out1<<<dim3(BB, 4), 128>>>(Wkv, bkv);
    k_out2<<<dim3(BB, 2), 256>>>(Wfc, bfc, out);
}

// round 8
// speedup vs baseline: 1.4305x; 1.4305x over previous
#include <cuda_runtime.h>

#define BB 32
#define CC 256
#define TT 4096
#define NH 8
#define DH 64
#define DK 512   // NH*DH

typedef unsigned long long u64;

// Scratch (allocation-free per harness rules)
__device__ float g_qW[BB * NH * CC];        // scale-folded q @ Wkv_k
__device__ float g_pl[4][BB * NH * TT];     // partial logits, 4 c-quarters
__device__ float g_attn[BB * NH * TT];      // softmax output
__device__ float g_xp[2][BB * NH * CC];     // xattn partials, 2 j-halves
__device__ float g_oh[BB * DK];             // v-projection intermediate

// ---- packed f32x2 helpers (Blackwell FFMA2) ----
__device__ __forceinline__ u64 pk(float a, float b) {
    u64 v; asm("mov.b64 %0,{%1,%2};" : "=l"(v) : "f"(a), "f"(b)); return v;
}
__device__ __forceinline__ float2 upk(u64 v) {
    float2 f; asm("mov.b64 {%0,%1},%2;" : "=f"(f.x), "=f"(f.y) : "l"(v)); return f;
}
__device__ __forceinline__ void ffma2(u64& d, u64 a, u64 b) {
    asm("fma.rn.f32x2 %0,%1,%2,%0;" : "+l"(d) : "l"(a), "l"(b));
}

// ---------------------------------------------------------------------------
// Kernel A: per (n,b): q = query@Wq.T + bq ; qW[b,n,c] = scale * q·Wkv_k[:,c]
// grid = (8 n, 32 b), 256 threads
// ---------------------------------------------------------------------------
__global__ void k_prep(const float* __restrict__ query,
                       const float* __restrict__ Wq,
                       const float* __restrict__ bq,
                       const float* __restrict__ Wkv) {
    const int n = blockIdx.x, b = blockIdx.y;
    const int tid = threadIdx.x, wid = tid >> 5, lane = tid & 31;
    __shared__ float qin[CC];
    __shared__ float qs[DH];

    qin[tid] = query[b * CC + tid];
    __syncthreads();

    const float4* qv = (const float4*)qin;
    for (int d = wid; d < DH; d += 8) {
        const float4* wr = (const float4*)(Wq + (size_t)(n * DH + d) * CC);
        float s = 0.f;
#pragma unroll
        for (int i = 0; i < 2; ++i) {
            const float4 w = wr[lane + i * 32];
            const float4 q4 = qv[lane + i * 32];
            s += w.x * q4.x + w.y * q4.y + w.z * q4.z + w.w * q4.w;
        }
#pragma unroll
        for (int o = 16; o; o >>= 1) s += __shfl_xor_sync(~0u, s, o);
        if (!lane) qs[d] = s + bq[n * DH + d];
    }
    __syncthreads();

    const float* wbase = Wkv + (size_t)(n * DH) * CC + tid;
    float s = 0.f;
#pragma unroll 8
    for (int d = 0; d < DH; ++d) s += qs[d] * wbase[(size_t)d * CC];
    g_qW[(b * NH + n) * CC + tid] = s * 0.125f;  // 1/sqrt(64)
}

// ---------------------------------------------------------------------------
// Kernel B: partial logits, c in quarters; FFMA2 math.
// grid = (4 j-tiles of 1024, 4 c-quarters, 32 b), 256 threads.
// ---------------------------------------------------------------------------
__global__ void __launch_bounds__(256) k_logits(const float* __restrict__ x) {
    const int b = blockIdx.z;
    const int cq = blockIdx.y;
    const int jq = blockIdx.x * 256 + threadIdx.x;   // 16B-unit index into j

    __shared__ u64 qw2[64][NH];                      // packed {w,w}, 4 KB
    for (int i = threadIdx.x; i < 64 * NH; i += 256) {
        const int c = i >> 3, n = i & 7;
        const float w = g_qW[(b * NH + n) * CC + cq * 64 + c];
        qw2[c][n] = pk(w, w);
    }
    __syncthreads();

    u64 acc2[NH][2];
#pragma unroll
    for (int n = 0; n < NH; ++n) { acc2[n][0] = 0ull; acc2[n][1] = 0ull; }

    const ulonglong2* xp =
        (const ulonglong2*)(x + ((size_t)b * CC + cq * 64) * TT) + jq;
#pragma unroll 8
    for (int c = 0; c < 64; ++c) {
        const ulonglong2 xv = __ldcs(&xp[(size_t)c * (TT / 4)]);
#pragma unroll
        for (int n = 0; n < NH; ++n) {
            const u64 w = qw2[c][n];
            ffma2(acc2[n][0], w, xv.x);
            ffma2(acc2[n][1], w, xv.y);
        }
    }

#pragma unroll
    for (int n = 0; n < NH; ++n) {
        const float2 lo = upk(acc2[n][0]);
        const float2 hi = upk(acc2[n][1]);
        ((float4*)(g_pl[cq] + (size_t)(b * NH + n) * TT))[jq] =
            make_float4(lo.x, lo.y, hi.x, hi.y);
    }
}

// ---------------------------------------------------------------------------
// Kernel C: logits = sum of 4 partials, softmax over j=4096.
// grid = 256 rows, 256 threads
// ---------------------------------------------------------------------------
__global__ void k_softmax() {
    const int row = blockIdx.x;
    const int tid = threadIdx.x;
    float4* pa = (float4*)(g_attn + (size_t)row * TT);

    float4 v[4];
#pragma unroll
    for (int i = 0; i < 4; ++i) {
        float4 a = ((const float4*)(g_pl[0] + (size_t)row * TT))[tid + i * 256];
#pragma unroll
        for (int p = 1; p < 4; ++p) {
            const float4 c = ((const float4*)(g_pl[p] + (size_t)row * TT))[tid + i * 256];
            a.x += c.x; a.y += c.y; a.z += c.z; a.w += c.w;
        }
        v[i] = a;
    }

    float m = -1e30f;
#pragma unroll
    for (int i = 0; i < 4; ++i)
        m = fmaxf(m, fmaxf(fmaxf(v[i].x, v[i].y), fmaxf(v[i].z, v[i].w)));

    __shared__ float red[8];
#pragma unroll
    for (int o = 16; o; o >>= 1) m = fmaxf(m, __shfl_xor_sync(~0u, m, o));
    if ((tid & 31) == 0) red[tid >> 5] = m;
    __syncthreads();
    m = red[0];
#pragma unroll
    for (int i = 1; i < 8; ++i) m = fmaxf(m, red[i]);
    __syncthreads();

    float s = 0.f;
#pragma unroll
    for (int i = 0; i < 4; ++i) {
        v[i].x = __expf(v[i].x - m); v[i].y = __expf(v[i].y - m);
        v[i].z = __expf(v[i].z - m); v[i].w = __expf(v[i].w - m);
        s += v[i].x + v[i].y + v[i].z + v[i].w;
    }
#pragma unroll
    for (int o = 16; o; o >>= 1) s += __shfl_xor_sync(~0u, s, o);
    if ((tid & 31) == 0) red[tid >> 5] = s;
    __syncthreads();
    s = red[0];
#pragma unroll
    for (int i = 1; i < 8; ++i) s += red[i];

    const float inv = 1.f / s;
#pragma unroll
    for (int i = 0; i < 4; ++i) {
        v[i].x *= inv; v[i].y *= inv; v[i].z *= inv; v[i].w *= inv;
        pa[tid + i * 256] = v[i];
    }
}

// ---------------------------------------------------------------------------
// Kernel D: xattn partial over j-half; FFMA2 math.
// grid = (8 c-tiles of 32, 2 jh, 32 b), 256 threads = 8 warps, warp owns 4 c.
// ---------------------------------------------------------------------------
__global__ void __launch_bounds__(256, 2) k_xattn(const float* __restrict__ x) {
    const int b = blockIdx.z;
    const int jh = blockIdx.y;
    const int cbase = blockIdx.x * 32 + (threadIdx.x >> 5) * 4;
    const int tid = threadIdx.x;
    const int lane = tid & 31;

    __shared__ u64 attn2[NH][512];  // one 1024-j chunk as f32x2 pairs, 32 KB

    u64 acc2[NH][4];
#pragma unroll
    for (int n = 0; n < NH; ++n)
#pragma unroll
        for (int cc = 0; cc < 4; ++cc) acc2[n][cc] = 0ull;

    const ulonglong2* ap = (const ulonglong2*)(g_attn + (size_t)b * NH * TT);

    for (int chunk = 0; chunk < 2; ++chunk) {
        const int jq0 = jh * 512 + chunk * 256;  // 16B-unit index of chunk start
        __syncthreads();
        for (int i = tid; i < NH * 256; i += 256)
            ((ulonglong2*)attn2[i >> 8])[i & 255] =
                ap[(i >> 8) * (TT / 4) + jq0 + (i & 255)];
        __syncthreads();

        const ulonglong2* xq = (const ulonglong2*)(x + (size_t)b * CC * TT) + jq0;
#pragma unroll
        for (int step = 0; step < 8; step += 2) {
            const int q1 = lane + step * 32;
            const int q2 = q1 + 32;
            ulonglong2 xv1[4], xv2[4];
#pragma unroll
            for (int cc = 0; cc < 4; ++cc) {
                xv1[cc] = __ldcs(&xq[(size_t)(cbase + cc) * (TT / 4) + q1]);
                xv2[cc] = __ldcs(&xq[(size_t)(cbase + cc) * (TT / 4) + q2]);
            }
#pragma unroll
            for (int n = 0; n < NH; ++n) {
                const ulonglong2 a1 = ((const ulonglong2*)attn2[n])[q1];
                const ulonglong2 a2 = ((const ulonglong2*)attn2[n])[q2];
#pragma unroll
                for (int cc = 0; cc < 4; ++cc) {
                    ffma2(acc2[n][cc], a1.x, xv1[cc].x);
                    ffma2(acc2[n][cc], a1.y, xv1[cc].y);
                    ffma2(acc2[n][cc], a2.x, xv2[cc].x);
                    ffma2(acc2[n][cc], a2.y, xv2[cc].y);
                }
            }
        }
    }

#pragma unroll
    for (int n = 0; n < NH; ++n)
#pragma unroll
        for (int cc = 0; cc < 4; ++cc) {
            const float2 f = upk(acc2[n][cc]);
            float v = f.x + f.y;
#pragma unroll
            for (int o = 16; o; o >>= 1) v += __shfl_xor_sync(~0u, v, o);
            if (lane == 0) g_xp[jh][(size_t)(b * NH + n) * CC + cbase + cc] = v;
        }
}

// ---------------------------------------------------------------------------
// Kernel E1: oh[b,nd] = Wkv_v[nd]·xa[b,n] + bkv_v[nd]
// grid = (16 nd-tiles of 32, 4 b-groups of 8), 256 threads, thread-per-output.
// Weights staged in smem once; bank-conflict-free padded tiles.
// ---------------------------------------------------------------------------
__global__ void __launch_bounds__(256) k_out1(const float* __restrict__ Wkv,
                                              const float* __restrict__ bkv) {
    const int ndt = blockIdx.x, bg = blockIdx.y;
    const int n = ndt >> 1;                 // head of this 32-row nd tile
    const int tid = threadIdx.x;
    __shared__ float ws[32][260];           // 32 weight rows, padded
    __shared__ float xs[8][260];            // 8 batches of xattn, padded

    const float4* wsrc = (const float4*)(Wkv + (size_t)(DK + ndt * 32) * CC);
    for (int i = tid; i < 32 * 64; i += 256)
        *(float4*)&ws[i >> 6][(i & 63) * 4] = wsrc[i];
    for (int i = tid; i < 8 * 64; i += 256) {
        const int bl = i >> 6, c4 = i & 63;
        const size_t gi = ((size_t)((bg * 8 + bl) * NH + n)) * CC + c4 * 4;
        const float4 a = *(const float4*)&g_xp[0][gi];
        const float4 c = *(const float4*)&g_xp[1][gi];
        *(float4*)&xs[bl][c4 * 4] = make_float4(a.x + c.x, a.y + c.y, a.z + c.z, a.w + c.w);
    }
    __syncthreads();

    const int ndl = tid >> 3, bl = tid & 7;
    float acc = 0.f;
#pragma unroll 8
    for (int c4 = 0; c4 < 64; ++c4) {
        const float4 w = *(const float4*)&ws[ndl][c4 * 4];
        const float4 v = *(const float4*)&xs[bl][c4 * 4];
        acc += w.x * v.x + w.y * v.y + w.z * v.z + w.w * v.w;
    }
    const int nd = ndt * 32 + ndl;
    g_oh[(bg * 8 + bl) * DK + nd] = acc + bkv[DK + nd];
}

// ---------------------------------------------------------------------------
// Kernel E2: y[b,o] = relu(oh[b]·Wfc[o] + bfc[o])
// grid = (8 o-tiles of 32, 4 b-groups of 8), 256 threads, thread-per-output.
// ---------------------------------------------------------------------------
__global__ void __launch_bounds__(256) k_out2(const float* __restrict__ Wfc,
                                              const float* __restrict__ bfc,
                                              float* __restrict__ out) {
    const int ot = blockIdx.x, bg = blockIdx.y;
    const int tid = threadIdx.x;
    __shared__ float ws[32][516];           // 32 weight rows (DK=512), padded
    __shared__ float xs[8][516];            // 8 batches of oh, padded

    const float4* wsrc = (const float4*)(Wfc + (size_t)(ot * 32) * DK);
    for (int i = tid; i < 32 * 128; i += 256)
        *(float4*)&ws[i >> 7][(i & 127) * 4] = wsrc[i];
    for (int i = tid; i < 8 * 128; i += 256) {
        const int bl = i >> 7, k4 = i & 127;
        *(float4*)&xs[bl][k4 * 4] =
            *(const float4*)&g_oh[(bg * 8 + bl) * DK + k4 * 4];
    }
    __syncthreads();

    const int ol = tid >> 3, bl = tid & 7;
    float acc = 0.f;
#pragma unroll 8
    for (int k4 = 0; k4 < 128; ++k4) {
        const float4 w = *(const float4*)&ws[ol][k4 * 4];
        const float4 v = *(const float4*)&xs[bl][k4 * 4];
        acc += w.x * v.x + w.y * v.y + w.z * v.z + w.w * v.w;
    }
    const int o = ot * 32 + ol;
    out[(bg * 8 + bl) * CC + o] = fmaxf(acc + bfc[o], 0.f);
}

// ---------------------------------------------------------------------------
extern "C" void kernel_launch(void* const* d_in, const int* in_sizes, int n_in,
                              void* d_out, int out_size) {
    const float* x     = (const float*)d_in[0];  // (32,256,64,64)
    const float* query = (const float*)d_in[1];  // (32,256)
    const float* Wkv   = (const float*)d_in[2];  // (1024,256)
    const float* bkv   = (const float*)d_in[3];  // (1024)
    const float* Wq    = (const float*)d_in[4];  // (512,256)
    const float* bq    = (const float*)d_in[5];  // (512)
    const float* Wfc   = (const float*)d_in[6];  // (256,512)
    const float* bfc   = (const float*)d_in[7];  // (256)
    float* out = (float*)d_out;                  // (32,256)

    k_prep<<<dim3(NH, BB), 256>>>(query, Wq, bq, Wkv);
    k_logits<<<dim3(TT / 1024, 4, BB), 256>>>(x);
    k_softmax<<<BB * NH, 256>>>();
    k_xattn<<<dim3(CC / 32, 2, BB), 256>>>(x);
    k_out1<<<dim3(16, 4), 256>>>(Wkv, bkv);
    k_out2<<<dim3(NH, 4), 256>>>(Wfc, bfc, out);
}

// round 9
// speedup vs baseline: 1.4987x; 1.0476x over previous
#include <cuda_runtime.h>

#define BB 32
#define CC 256
#define TT 4096
#define NH 8
#define DH 64
#define DK 512   // NH*DH

typedef unsigned long long u64;

// Scratch (allocation-free per harness rules)
__device__ float g_qW[BB * NH * CC];        // scale-folded q @ Wkv_k
__device__ float g_pl[2][BB * NH * TT];     // partial logits, 2 c-halves
__device__ float g_attn[BB * NH * TT];      // softmax output
__device__ float g_xp[2][BB * NH * CC];     // xattn partials, 2 j-halves
__device__ float g_oh[BB * DK];             // v-projection intermediate

// ---- packed f32x2 helpers (Blackwell FFMA2) ----
__device__ __forceinline__ u64 pk(float a, float b) {
    u64 v; asm("mov.b64 %0,{%1,%2};" : "=l"(v) : "f"(a), "f"(b)); return v;
}
__device__ __forceinline__ float2 upk(u64 v) {
    float2 f; asm("mov.b64 {%0,%1},%2;" : "=f"(f.x), "=f"(f.y) : "l"(v)); return f;
}
__device__ __forceinline__ void ffma2(u64& d, u64 a, u64 b) {
    asm("fma.rn.f32x2 %0,%1,%2,%0;" : "+l"(d) : "l"(a), "l"(b));
}

// ---------------------------------------------------------------------------
// Kernel A: per (n,b): q = query@Wq.T + bq ; qW[b,n,c] = scale * q·Wkv_k[:,c]
// grid = (8 n, 32 b), 256 threads
// ---------------------------------------------------------------------------
__global__ void k_prep(const float* __restrict__ query,
                       const float* __restrict__ Wq,
                       const float* __restrict__ bq,
                       const float* __restrict__ Wkv) {
    const int n = blockIdx.x, b = blockIdx.y;
    const int tid = threadIdx.x, wid = tid >> 5, lane = tid & 31;
    __shared__ float qin[CC];
    __shared__ float qs[DH];

    qin[tid] = query[b * CC + tid];
    __syncthreads();

    const float4* qv = (const float4*)qin;
    for (int d = wid; d < DH; d += 8) {
        const float4* wr = (const float4*)(Wq + (size_t)(n * DH + d) * CC);
        float s = 0.f;
#pragma unroll
        for (int i = 0; i < 2; ++i) {
            const float4 w = wr[lane + i * 32];
            const float4 q4 = qv[lane + i * 32];
            s += w.x * q4.x + w.y * q4.y + w.z * q4.z + w.w * q4.w;
        }
#pragma unroll
        for (int o = 16; o; o >>= 1) s += __shfl_xor_sync(~0u, s, o);
        if (!lane) qs[d] = s + bq[n * DH + d];
    }
    __syncthreads();

    const float* wbase = Wkv + (size_t)(n * DH) * CC + tid;
    float s = 0.f;
#pragma unroll 8
    for (int d = 0; d < DH; ++d) s += qs[d] * wbase[(size_t)d * CC];
    g_qW[(b * NH + n) * CC + tid] = s * 0.125f;  // 1/sqrt(64)
}

// ---------------------------------------------------------------------------
// Kernel B: partial logits, c in halves; FFMA2 math.
// grid = (4 j-tiles of 1024, 2 c-halves, 32 b), 256 threads.
// ---------------------------------------------------------------------------
__global__ void __launch_bounds__(256) k_logits(const float* __restrict__ x) {
    const int b = blockIdx.z;
    const int ch = blockIdx.y;
    const int jq = blockIdx.x * 256 + threadIdx.x;   // 16B-unit index into j

    __shared__ u64 qw2[128][NH];                     // packed {w,w}, 8 KB
    for (int i = threadIdx.x; i < 128 * NH; i += 256) {
        const int c = i >> 3, n = i & 7;
        const float w = g_qW[(b * NH + n) * CC + ch * 128 + c];
        qw2[c][n] = pk(w, w);
    }
    __syncthreads();

    u64 acc2[NH][2];
#pragma unroll
    for (int n = 0; n < NH; ++n) { acc2[n][0] = 0ull; acc2[n][1] = 0ull; }

    const ulonglong2* xp =
        (const ulonglong2*)(x + ((size_t)b * CC + ch * 128) * TT) + jq;
#pragma unroll 8
    for (int c = 0; c < 128; ++c) {
        const ulonglong2 xv = __ldcs(&xp[(size_t)c * (TT / 4)]);
#pragma unroll
        for (int n = 0; n < NH; ++n) {
            const u64 w = qw2[c][n];
            ffma2(acc2[n][0], w, xv.x);
            ffma2(acc2[n][1], w, xv.y);
        }
    }

#pragma unroll
    for (int n = 0; n < NH; ++n) {
        const float2 lo = upk(acc2[n][0]);
        const float2 hi = upk(acc2[n][1]);
        ((float4*)(g_pl[ch] + (size_t)(b * NH + n) * TT))[jq] =
            make_float4(lo.x, lo.y, hi.x, hi.y);
    }
}

// ---------------------------------------------------------------------------
// Kernel C: logits = p0 + p1, softmax over j=4096. grid = 256 rows, 256 thr.
// ---------------------------------------------------------------------------
__global__ void k_softmax() {
    const int row = blockIdx.x;
    const int tid = threadIdx.x;
    const float4* p0 = (const float4*)(g_pl[0] + (size_t)row * TT);
    const float4* p1 = (const float4*)(g_pl[1] + (size_t)row * TT);
    float4* pa = (float4*)(g_attn + (size_t)row * TT);

    float4 v[4];
#pragma unroll
    for (int i = 0; i < 4; ++i) {
        const float4 a = p0[tid + i * 256];
        const float4 b = p1[tid + i * 256];
        v[i] = make_float4(a.x + b.x, a.y + b.y, a.z + b.z, a.w + b.w);
    }

    float m = -1e30f;
#pragma unroll
    for (int i = 0; i < 4; ++i)
        m = fmaxf(m, fmaxf(fmaxf(v[i].x, v[i].y), fmaxf(v[i].z, v[i].w)));

    __shared__ float red[8];
#pragma unroll
    for (int o = 16; o; o >>= 1) m = fmaxf(m, __shfl_xor_sync(~0u, m, o));
    if ((tid & 31) == 0) red[tid >> 5] = m;
    __syncthreads();
    m = red[0];
#pragma unroll
    for (int i = 1; i < 8; ++i) m = fmaxf(m, red[i]);
    __syncthreads();

    float s = 0.f;
#pragma unroll
    for (int i = 0; i < 4; ++i) {
        v[i].x = __expf(v[i].x - m); v[i].y = __expf(v[i].y - m);
        v[i].z = __expf(v[i].z - m); v[i].w = __expf(v[i].w - m);
        s += v[i].x + v[i].y + v[i].z + v[i].w;
    }
#pragma unroll
    for (int o = 16; o; o >>= 1) s += __shfl_xor_sync(~0u, s, o);
    if ((tid & 31) == 0) red[tid >> 5] = s;
    __syncthreads();
    s = red[0];
#pragma unroll
    for (int i = 1; i < 8; ++i) s += red[i];

    const float inv = 1.f / s;
#pragma unroll
    for (int i = 0; i < 4; ++i) {
        v[i].x *= inv; v[i].y *= inv; v[i].z *= inv; v[i].w *= inv;
        pa[tid + i * 256] = v[i];
    }
}

// ---------------------------------------------------------------------------
// Kernel D: xattn partial over j-half (R6-exact math; reverse chunk order for
// L2 reuse of x left behind by k_logits).
// grid = (8 c-tiles of 32, 2 jh, 32 b), 256 threads = 8 warps, warp owns 4 c.
// ---------------------------------------------------------------------------
__global__ void __launch_bounds__(256, 2) k_xattn(const float* __restrict__ x) {
    const int b = blockIdx.z;
    const int jh = blockIdx.y;
    const int cbase = blockIdx.x * 32 + (threadIdx.x >> 5) * 4;
    const int tid = threadIdx.x;
    const int lane = tid & 31;

    __shared__ float4 attn_s[NH][256];  // one 1024-j chunk, 32 KB

    float acc[NH][4];
#pragma unroll
    for (int n = 0; n < NH; ++n)
#pragma unroll
        for (int cc = 0; cc < 4; ++cc) acc[n][cc] = 0.f;

    const float4* ap = (const float4*)(g_attn + (size_t)b * NH * TT);

    for (int chunk = 1; chunk >= 0; --chunk) {   // high j first (L2-freshest)
        const int jq0 = jh * 512 + chunk * 256;  // float4 index of chunk start
        __syncthreads();
        for (int i = tid; i < NH * 256; i += 256)
            attn_s[i >> 8][i & 255] = ap[(i >> 8) * (TT / 4) + jq0 + (i & 255)];
        __syncthreads();

        const float4* xp = (const float4*)(x + (size_t)b * CC * TT) + jq0;
#pragma unroll
        for (int step = 0; step < 8; step += 4) {
            // Batch all 16 loads first: maximize outstanding LDG.128
            float4 xv[4][4];
#pragma unroll
            for (int u = 0; u < 4; ++u) {
                const int q = lane + (step + u) * 32;
#pragma unroll
                for (int cc = 0; cc < 4; ++cc)
                    xv[u][cc] = __ldcs(&xp[(size_t)(cbase + cc) * (TT / 4) + q]);
            }
#pragma unroll
            for (int u = 0; u < 4; ++u) {
                const int q = lane + (step + u) * 32;
#pragma unroll
                for (int n = 0; n < NH; ++n) {
                    const float4 a = attn_s[n][q];
#pragma unroll
                    for (int cc = 0; cc < 4; ++cc)
                        acc[n][cc] += a.x * xv[u][cc].x + a.y * xv[u][cc].y +
                                      a.z * xv[u][cc].z + a.w * xv[u][cc].w;
                }
            }
        }
    }

#pragma unroll
    for (int n = 0; n < NH; ++n)
#pragma unroll
        for (int cc = 0; cc < 4; ++cc) {
            float v = acc[n][cc];
#pragma unroll
            for (int o = 16; o; o >>= 1) v += __shfl_xor_sync(~0u, v, o);
            if (lane == 0) g_xp[jh][(size_t)(b * NH + n) * CC + cbase + cc] = v;
        }
}

// ---------------------------------------------------------------------------
// Kernel E1: oh[b,nd] = Wkv_v[nd]·xa[b,n] + bkv_v[nd]
// grid = (16 nd-tiles of 32, 4 b-groups of 8), 256 threads, thread-per-output.
// ---------------------------------------------------------------------------
__global__ void __launch_bounds__(256) k_out1(const float* __restrict__ Wkv,
                                              const float* __restrict__ bkv) {
    const int ndt = blockIdx.x, bg = blockIdx.y;
    const int n = ndt >> 1;                 // head of this 32-row nd tile
    const int tid = threadIdx.x;
    __shared__ float ws[32][260];           // 32 weight rows, padded
    __shared__ float xs[8][260];            // 8 batches of xattn, padded

    const float4* wsrc = (const float4*)(Wkv + (size_t)(DK + ndt * 32) * CC);
    for (int i = tid; i < 32 * 64; i += 256)
        *(float4*)&ws[i >> 6][(i & 63) * 4] = wsrc[i];
    for (int i = tid; i < 8 * 64; i += 256) {
        const int bl = i >> 6, c4 = i & 63;
        const size_t gi = ((size_t)((bg * 8 + bl) * NH + n)) * CC + c4 * 4;
        const float4 a = *(const float4*)&g_xp[0][gi];
        const float4 c = *(const float4*)&g_xp[1][gi];
        *(float4*)&xs[bl][c4 * 4] = make_float4(a.x + c.x, a.y + c.y, a.z + c.z, a.w + c.w);
    }
    __syncthreads();

    const int ndl = tid >> 3, bl = tid & 7;
    float acc = 0.f;
#pragma unroll 8
    for (int c4 = 0; c4 < 64; ++c4) {
        const float4 w = *(const float4*)&ws[ndl][c4 * 4];
        const float4 v = *(const float4*)&xs[bl][c4 * 4];
        acc += w.x * v.x + w.y * v.y + w.z * v.z + w.w * v.w;
    }
    const int nd = ndt * 32 + ndl;
    g_oh[(bg * 8 + bl) * DK + nd] = acc + bkv[DK + nd];
}

// ---------------------------------------------------------------------------
// Kernel E2: y[b,o] = relu(oh[b]·Wfc[o] + bfc[o])
// grid = (8 o-tiles of 32, 4 b-groups of 8), 256 threads, thread-per-output.
// ---------------------------------------------------------------------------
__global__ void __launch_bounds__(256) k_out2(const float* __restrict__ Wfc,
                                              const float* __restrict__ bfc,
                                              float* __restrict__ out) {
    const int ot = blockIdx.x, bg = blockIdx.y;
    const int tid = threadIdx.x;
    __shared__ float ws[32][516];           // 32 weight rows (DK=512), padded
    __shared__ float xs[8][516];            // 8 batches of oh, padded

    const float4* wsrc = (const float4*)(Wfc + (size_t)(ot * 32) * DK);
    for (int i = tid; i < 32 * 128; i += 256)
        *(float4*)&ws[i >> 7][(i & 127) * 4] = wsrc[i];
    for (int i = tid; i < 8 * 128; i += 256) {
        const int bl = i >> 7, k4 = i & 127;
        *(float4*)&xs[bl][k4 * 4] =
            *(const float4*)&g_oh[(bg * 8 + bl) * DK + k4 * 4];
    }
    __syncthreads();

    const int ol = tid >> 3, bl = tid & 7;
    float acc = 0.f;
#pragma unroll 8
    for (int k4 = 0; k4 < 128; ++k4) {
        const float4 w = *(const float4*)&ws[ol][k4 * 4];
        const float4 v = *(const float4*)&xs[bl][k4 * 4];
        acc += w.x * v.x + w.y * v.y + w.z * v.z + w.w * v.w;
    }
    const int o = ot * 32 + ol;
    out[(bg * 8 + bl) * CC + o] = fmaxf(acc + bfc[o], 0.f);
}

// ---------------------------------------------------------------------------
extern "C" void kernel_launch(void* const* d_in, const int* in_sizes, int n_in,
                              void* d_out, int out_size) {
    const float* x     = (const float*)d_in[0];  // (32,256,64,64)
    const float* query = (const float*)d_in[1];  // (32,256)
    const float* Wkv   = (const float*)d_in[2];  // (1024,256)
    const float* bkv   = (const float*)d_in[3];  // (1024)
    const float* Wq    = (const float*)d_in[4];  // (512,256)
    const float* bq    = (const float*)d_in[5];  // (512)
    const float* Wfc   = (const float*)d_in[6];  // (256,512)
    const float* bfc   = (const float*)d_in[7];  // (256)
    float* out = (float*)d_out;                  // (32,256)

    k_prep<<<dim3(NH, BB), 256>>>(query, Wq, bq, Wkv);
    k_logits<<<dim3(TT / 1024, 2, BB), 256>>>(x);
    k_softmax<<<BB * NH, 256>>>();
    k_xattn<<<dim3(CC / 32, 2, BB), 256>>>(x);
    k_out1<<<dim3(16, 4), 256>>>(Wkv, bkv);
    k_out2<<<dim3(NH, 4), 256>>>(Wfc, bfc, out);
}